// round 7
// baseline (speedup 1.0000x reference)
#include <cuda_runtime.h>
#include <cstdint>

#define N_BATCH 256
#define C_DIM   2048
#define HW      49
#define TOTAL   (C_DIM * HW)          // 100352 floats per batch
#define THREADS 512
#define ACTIVE  490                   // 49 * 10 active loader threads
#define QMAX    10                    // threads per p-bucket
#define FULL_ITERS 204                // 204*490 = 99960; tail covers the rest (tid < 392)
#define TAIL_ACTIVE 392               // 100352 - 99960

// smem layout (floats): wpack float4[C_DIM] (8192 f) | part [5][THREADS] (2560 f) | buckets [5][HW]
#define OFF_WPACK   0
#define OFF_PART    (4 * C_DIM)
#define OFF_BUCKET  (OFF_PART + 5 * THREADS)
#define SMEM_FLOATS (OFF_BUCKET + 5 * HW)
#define SMEM_BYTES  (SMEM_FLOATS * 4)          // 32768 + 10240 + 980 = 43988 B

// Packed f32x2 helpers (ptxas never emits FFMA2 from plain C++)
__device__ __forceinline__ void pack_dup(uint64_t& dst, float v) {
    asm("mov.b64 %0, {%1, %1};" : "=l"(dst) : "r"(__float_as_uint(v)));
}
__device__ __forceinline__ void fma2(uint64_t& acc, uint64_t xx, uint64_t ww) {
    asm("fma.rn.f32x2 %0, %1, %2, %0;" : "+l"(acc) : "l"(xx), "l"(ww));
}

// One CTA per batch n. Barrier-free streaming mainloop: grid-stride LDG over
// x[n] with stride 490 (multiple of 49) so each thread's spatial index p is
// fixed; register accumulators; deterministic smem tree-combine; fused epilogue.
__global__ void __launch_bounds__(THREADS, 2)
rcp_stream_kernel(const float* __restrict__ x, const float* __restrict__ mask,
                  const float* __restrict__ W, const float* __restrict__ bvec,
                  float* __restrict__ out) {
    const int n    = blockIdx.x;
    const int tid  = threadIdx.x;
    const int wid  = tid >> 5;
    const int lane = tid & 31;

    extern __shared__ float smem[];
    float4* wpack = reinterpret_cast<float4*>(smem + OFF_WPACK);   // [C_DIM]
    float*  part  = smem + OFF_PART;                               // [5][THREADS]
    float*  rS    = smem + OFF_BUCKET;                             // [5][HW]
    float*  rA0   = rS + HW;
    float*  rA1   = rS + 2 * HW;
    float*  rD0   = rS + 3 * HW;
    float*  rD1   = rS + 4 * HW;

    // Stage W packed: {A0w, A1w, D0w, D1w} per c.
    // W layout (2, 4096): W[o*4096 + c] first half (max_features), W[o*4096+2048+c] second.
    for (int c = tid; c < C_DIM; c += THREADS) {
        wpack[c] = make_float4(W[c], W[4096 + c], W[2048 + c], W[6144 + c]);
    }
    __syncthreads();   // wpack ready (only CTA-wide barrier before the combine)

    float    accS = 0.0f;
    uint64_t accA = 0;   // packed (a0, a1)
    uint64_t accD = 0;   // packed (d0, d1)

    if (tid < ACTIVE) {
        const int q = tid / HW;          // 0..9
        const float* xp = x + (size_t)n * TOTAL + tid;
        const ulonglong2* wp2 = reinterpret_cast<const ulonglong2*>(wpack);

        #pragma unroll 4
        for (int i = 0; i < FULL_ITERS; i++) {
            float xv = __ldg(xp + i * ACTIVE);
            ulonglong2 w2 = wp2[QMAX * i + q];      // LDS.128, warp-broadcast
            uint64_t xx; pack_dup(xx, xv);
            accS += xv;
            fma2(accA, xx, w2.x);
            fma2(accD, xx, w2.y);
        }
        if (tid < TAIL_ACTIVE) {                    // i = FULL_ITERS partial
            float xv = __ldg(xp + FULL_ITERS * ACTIVE);
            ulonglong2 w2 = wp2[QMAX * FULL_ITERS + q];
            uint64_t xx; pack_dup(xx, xv);
            accS += xv;
            fma2(accA, xx, w2.x);
            fma2(accD, xx, w2.y);
        }
    }

    // Publish per-thread partials.
    part[0 * THREADS + tid] = accS;
    part[1 * THREADS + tid] = __uint_as_float((uint32_t)(accA & 0xFFFFFFFFu));
    part[2 * THREADS + tid] = __uint_as_float((uint32_t)(accA >> 32));
    part[3 * THREADS + tid] = __uint_as_float((uint32_t)(accD & 0xFFFFFFFFu));
    part[4 * THREADS + tid] = __uint_as_float((uint32_t)(accD >> 32));
    __syncthreads();

    // Deterministic bucket combine: thread p (< 49) sums its 10 contributors.
    if (tid < HW) {
        #pragma unroll
        for (int k = 0; k < 5; k++) {
            const float* pk = part + k * THREADS;
            float v = 0.0f;
            #pragma unroll
            for (int q = 0; q < QMAX; q++) v += pk[q * HW + tid];
            rS[k * HW + tid] = v;       // rS is base of the 5 bucket arrays
        }
    }
    __syncthreads();

    // ---- Fused epilogue: warp 0 only ----
    if (wid == 0) {
        const float* m = mask + n * HW;

        // threshold = mean(mask)
        float m0 = m[lane];                                   // lane < 32 <= 49
        float m1 = (lane + 32 < HW) ? m[lane + 32] : 0.0f;
        float msum = m0 + m1;
        #pragma unroll
        for (int off = 16; off; off >>= 1) msum += __shfl_xor_sync(0xFFFFFFFFu, msum, off);
        const float thr = msum * (1.0f / 49.0f);

        // masked mean + argmax (first-index tie-break, matching jnp.argmax)
        float v0 = (m0 > thr) ? rS[lane] * (1.0f / (float)C_DIM) : 0.0f;
        float bv = v0;
        int   bi = lane;
        if (lane + 32 < HW) {
            float v1 = (m1 > thr) ? rS[lane + 32] * (1.0f / (float)C_DIM) : 0.0f;
            if (v1 > bv) { bv = v1; bi = lane + 32; }         // tie keeps smaller index
        }
        #pragma unroll
        for (int off = 16; off; off >>= 1) {
            float ov = __shfl_xor_sync(0xFFFFFFFFu, bv, off);
            int   oi = __shfl_xor_sync(0xFFFFFFFFu, bi, off);
            if (ov > bv || (ov == bv && oi < bi)) { bv = ov; bi = oi; }
        }
        const int pstar = bi;

        const float A0s = rA0[pstar];
        const float A1s = rA1[pstar];
        const float b0 = bvec[0], b1 = bvec[1];
        const float ai = (float)(pstar / 7);
        const float aj = (float)(pstar % 7);
        const float inv_pi = 0.318309886183790672f;

        float dist[2], gap[2];
        float gsum = 0.0f;
        #pragma unroll
        for (int t = 0; t < 2; t++) {
            int p = lane + 32 * t;
            if (p < HW) {
                float pd = fmaxf(A0s + rD0[p] + b0, 0.0f);
                float pa = fmaxf(A1s + rD1[p] + b1, 0.0f);
                if (p == pstar) { pd = 0.0f; pa = 0.0f; }
                float ri = ((float)(p / 7) - ai) * (1.0f / 7.0f);
                float rj = ((float)(p % 7) - aj) * (1.0f / 7.0f);
                float rd = sqrtf(ri * ri + rj * rj);
                float ra = (atan2f(rj, ri) * inv_pi + 1.0f) * 0.5f;
                float g  = pa - ra;
                if (g < 0.0f) g += 1.0f;
                float dl = pd - rd;
                dist[t] = dl * dl;
                gap[t]  = g;
                gsum   += g;
            } else {
                dist[t] = 0.0f; gap[t] = 0.0f;
            }
        }
        #pragma unroll
        for (int off = 16; off; off >>= 1) gsum += __shfl_xor_sync(0xFFFFFFFFu, gsum, off);
        const float gmean = gsum * (1.0f / 49.0f);

        #pragma unroll
        for (int t = 0; t < 2; t++) {
            int p = lane + 32 * t;
            if (p < HW) {
                float gg = gap[t] - gmean;
                out[n * HW + p] = dist[t] + gg * gg;
            }
        }
    }
}

extern "C" void kernel_launch(void* const* d_in, const int* in_sizes, int n_in,
                              void* d_out, int out_size) {
    const float* x    = (const float*)d_in[0];   // (256, 2048, 7, 7)
    const float* mask = (const float*)d_in[1];   // (256, 7, 7)
    const float* W    = (const float*)d_in[2];   // (2, 4096)
    const float* b    = (const float*)d_in[3];   // (2,)
    float* out = (float*)d_out;                  // (256, 7, 7)

    cudaFuncSetAttribute(rcp_stream_kernel,
                         cudaFuncAttributeMaxDynamicSharedMemorySize, SMEM_BYTES);

    rcp_stream_kernel<<<N_BATCH, THREADS, SMEM_BYTES>>>(x, mask, W, b, out);
}

// round 9
// speedup vs baseline: 1.6643x; 1.6643x over previous
#include <cuda_runtime.h>
#include <cstdint>

#define N_BATCH 256
#define C_DIM   2048
#define HW      49
#define CH      128                  // c-rows per staged chunk
#define NCHUNK  (C_DIM / CH)         // 16
#define ELEMS   (CH * HW)            // 6272 floats per chunk
#define CHUNK_BYTES (ELEMS * 4)      // 25088 B
#define NBUF    3
#define THREADS 288                  // 8 consumer warps + 1 producer warp
#define NCONS   8                    // consumer warps
// smem: mbar pad (32 floats: full[3], empty[3]) + wpack (float4[C_DIM]) + NBUF x-buffers
#define SMEM_MBAR_FLOATS 32
#define SMEM_FLOATS (SMEM_MBAR_FLOATS + 4 * C_DIM + NBUF * ELEMS)
#define SMEM_BYTES  (SMEM_FLOATS * 4)   // 128 + 32768 + 75264 = 108160 B -> 2 CTAs/SM

__device__ __forceinline__ uint32_t smem_u32(const void* p) {
    return (uint32_t)__cvta_generic_to_shared(p);
}
__device__ __forceinline__ void mbar_init(uint32_t mbar, uint32_t count) {
    asm volatile("mbarrier.init.shared::cta.b64 [%0], %1;" :: "r"(mbar), "r"(count) : "memory");
}
__device__ __forceinline__ void mbar_expect_tx(uint32_t mbar, uint32_t bytes) {
    asm volatile("mbarrier.arrive.expect_tx.shared::cta.b64 _, [%0], %1;"
                 :: "r"(mbar), "r"(bytes) : "memory");
}
__device__ __forceinline__ void mbar_arrive(uint32_t mbar) {
    asm volatile("mbarrier.arrive.release.cta.shared::cta.b64 _, [%0];"
                 :: "r"(mbar) : "memory");
}
__device__ __forceinline__ void bulk_g2s(uint32_t smem_dst, const void* gsrc,
                                         uint32_t bytes, uint32_t mbar) {
    asm volatile("cp.async.bulk.shared::cta.global.mbarrier::complete_tx::bytes "
                 "[%0], [%1], %2, [%3];"
                 :: "r"(smem_dst), "l"(gsrc), "r"(bytes), "r"(mbar) : "memory");
}
__device__ __forceinline__ void mbar_wait(uint32_t mbar, uint32_t parity) {
    uint32_t done;
    asm volatile(
        "{\n\t.reg .pred p;\n\t"
        "mbarrier.try_wait.parity.acquire.cta.shared::cta.b64 p, [%1], %2;\n\t"
        "selp.b32 %0, 1, 0, p;\n\t}"
        : "=r"(done) : "r"(mbar), "r"(parity) : "memory");
    if (!done) {
        asm volatile(
            "{\n\t.reg .pred P1;\n\t"
            "WAIT_LOOP_%=:\n\t"
            "mbarrier.try_wait.parity.acquire.cta.shared::cta.b64 P1, [%0], %1, 0x989680;\n\t"
            "@P1 bra.uni WAIT_DONE_%=;\n\t"
            "bra.uni WAIT_LOOP_%=;\n\t"
            "WAIT_DONE_%=:\n\t}"
            :: "r"(mbar), "r"(parity) : "memory");
    }
}

// Packed f32x2 helpers (ptxas never emits FFMA2 from plain C++)
__device__ __forceinline__ void pack_dup(uint64_t& dst, float v) {
    asm("mov.b64 %0, {%1, %1};" : "=l"(dst) : "r"(__float_as_uint(v)));
}
__device__ __forceinline__ void fma2(uint64_t& acc, uint64_t xx, uint64_t ww) {
    asm("fma.rn.f32x2 %0, %1, %2, %0;" : "+l"(acc) : "l"(xx), "l"(ww));
}

// One CTA per batch n. Warp-specialized: warp 8 = TMA producer, warps 0-7
// consume chunks with per-warp mbarrier handshakes (no per-chunk CTA barrier).
__global__ void __launch_bounds__(THREADS, 2)
rcp_ws_kernel(const float* __restrict__ x, const float* __restrict__ mask,
              const float* __restrict__ W, const float* __restrict__ bvec,
              float* __restrict__ out) {
    const int n    = blockIdx.x;
    const int tid  = threadIdx.x;
    const int wid  = tid >> 5;
    const int lane = tid & 31;

    extern __shared__ float smem[];
    uint64_t* mbar_s = reinterpret_cast<uint64_t*>(smem);                  // full[3], empty[3]
    float4*   wpack  = reinterpret_cast<float4*>(smem + SMEM_MBAR_FLOATS); // [C_DIM]
    float*    xs     = smem + SMEM_MBAR_FLOATS + 4 * C_DIM;                // NBUF x ELEMS

    const uint32_t full0  = smem_u32(&mbar_s[0]);
    const uint32_t empty0 = smem_u32(&mbar_s[NBUF]);

    if (tid == 0) {
        #pragma unroll
        for (int b = 0; b < NBUF; b++) {
            mbar_init(full0  + 8 * b, 1);      // tx-based completion
            mbar_init(empty0 + 8 * b, NCONS);  // 8 consumer-warp arrivals
        }
    }

    // Stage W packed: {A0w, A1w, D0w, D1w} per c.
    // W layout (2, 4096): W[o*4096+c] first half (max_features), W[o*4096+2048+c] second.
    for (int c = tid; c < C_DIM; c += THREADS) {
        wpack[c] = make_float4(W[c], W[4096 + c], W[2048 + c], W[6144 + c]);
    }

    const float* xn = x + (size_t)n * (C_DIM * HW);

    __syncthreads();   // mbarrier init + wpack visible

    if (wid == NCONS) {
        // ---- Producer warp: single elected thread streams all chunks ----
        if (lane == 0) {
            int buf = 0;
            int pphase = 1;   // flips to 0 at the first wrap, BEFORE the first
                              // empty-wait at chunk==NBUF (1st completion = phase 0)
            for (int chunk = 0; chunk < NCHUNK; chunk++) {
                if (chunk >= NBUF) {
                    mbar_wait(empty0 + 8 * buf, pphase);   // consumers done w/ buf
                }
                uint32_t fb = full0 + 8 * buf;
                mbar_expect_tx(fb, CHUNK_BYTES);
                bulk_g2s(smem_u32(xs + buf * ELEMS), xn + chunk * ELEMS,
                         CHUNK_BYTES, fb);
                if (++buf == NBUF) { buf = 0; pphase ^= 1; }
            }
        }
    }

    float    s[7]    = {0,0,0,0,0,0,0};
    uint64_t accA[7] = {0,0,0,0,0,0,0};   // packed (a0, a1)
    uint64_t accD[7] = {0,0,0,0,0,0,0};   // packed (d0, d1)

    if (wid < NCONS) {
        // ---- Consumer warps: free-running, per-warp handshakes only ----
        int buf = 0, fphase = 0;
        for (int chunk = 0; chunk < NCHUNK; chunk++) {
            mbar_wait(full0 + 8 * buf, fphase);

            const float*      xb  = xs + buf * ELEMS;
            const ulonglong2* wp2 = reinterpret_cast<const ulonglong2*>(wpack + chunk * CH);

            #pragma unroll
            for (int it = 0; it < 4; it++) {
                const int cl = lane + 32 * it;
                ulonglong2 w2 = wp2[cl];            // LDS.128: {A0w,A1w},{D0w,D1w}
                const float* row = xb + cl * HW;

                float xv[6];
                #pragma unroll
                for (int i = 0; i < 6; i++) xv[i] = row[wid + 8 * i];  // p<=47 in-bounds

                #pragma unroll
                for (int i = 0; i < 6; i++) {
                    uint64_t xx; pack_dup(xx, xv[i]);
                    s[i] += xv[i];
                    fma2(accA[i], xx, w2.x);
                    fma2(accD[i], xx, w2.y);
                }
                if (wid == 0) {                     // i=6 -> p=48 only for wid 0
                    float x6 = row[48];
                    uint64_t xx; pack_dup(xx, x6);
                    s[6] += x6;
                    fma2(accA[6], xx, w2.x);
                    fma2(accD[6], xx, w2.y);
                }
            }

            __syncwarp();
            if (lane == 0) mbar_arrive(empty0 + 8 * buf);   // release buffer

            if (++buf == NBUF) { buf = 0; fphase ^= 1; }
        }
    }

    // Warp-level reduction; results to SMEM (wpack region is dead now).
    float* rS  = smem + SMEM_MBAR_FLOATS;
    float* rA0 = rS + HW;
    float* rA1 = rS + 2 * HW;
    float* rD0 = rS + 3 * HW;
    float* rD1 = rS + 4 * HW;

    __syncthreads();   // all consumers done; producer done
    if (wid < NCONS) {
        #pragma unroll
        for (int i = 0; i < 7; i++) {
            int p = wid + 8 * i;
            float vs = s[i];
            float u0 = __uint_as_float((uint32_t)(accA[i] & 0xFFFFFFFFu));
            float u1 = __uint_as_float((uint32_t)(accA[i] >> 32));
            float v0 = __uint_as_float((uint32_t)(accD[i] & 0xFFFFFFFFu));
            float v1 = __uint_as_float((uint32_t)(accD[i] >> 32));
            #pragma unroll
            for (int off = 16; off; off >>= 1) {
                vs += __shfl_xor_sync(0xFFFFFFFFu, vs, off);
                u0 += __shfl_xor_sync(0xFFFFFFFFu, u0, off);
                u1 += __shfl_xor_sync(0xFFFFFFFFu, u1, off);
                v0 += __shfl_xor_sync(0xFFFFFFFFu, v0, off);
                v1 += __shfl_xor_sync(0xFFFFFFFFu, v1, off);
            }
            if (lane == 0 && p < HW) {
                rS [p] = vs;
                rA0[p] = u0;
                rA1[p] = u1;
                rD0[p] = v0;
                rD1[p] = v1;
            }
        }
    }
    __syncthreads();

    // ---- Fused epilogue: warp 0 only ----
    if (wid == 0) {
        const float* m = mask + n * HW;

        // threshold = mean(mask)
        float m0 = m[lane];                                   // lane < 32 <= 49
        float m1 = (lane + 32 < HW) ? m[lane + 32] : 0.0f;
        float msum = m0 + m1;
        #pragma unroll
        for (int off = 16; off; off >>= 1) msum += __shfl_xor_sync(0xFFFFFFFFu, msum, off);
        const float thr = msum * (1.0f / 49.0f);

        // masked mean + argmax (first-index tie-break, matching jnp.argmax)
        float v0 = (m0 > thr) ? rS[lane] * (1.0f / (float)C_DIM) : 0.0f;
        float bv = v0;
        int   bi = lane;
        if (lane + 32 < HW) {
            float v1 = (m1 > thr) ? rS[lane + 32] * (1.0f / (float)C_DIM) : 0.0f;
            if (v1 > bv) { bv = v1; bi = lane + 32; }         // tie keeps smaller index
        }
        #pragma unroll
        for (int off = 16; off; off >>= 1) {
            float ov = __shfl_xor_sync(0xFFFFFFFFu, bv, off);
            int   oi = __shfl_xor_sync(0xFFFFFFFFu, bi, off);
            if (ov > bv || (ov == bv && oi < bi)) { bv = ov; bi = oi; }
        }
        const int pstar = bi;

        const float A0s = rA0[pstar];
        const float A1s = rA1[pstar];
        const float b0 = bvec[0], b1 = bvec[1];
        const float ai = (float)(pstar / 7);
        const float aj = (float)(pstar % 7);
        const float inv_pi = 0.318309886183790672f;

        float dist[2], gap[2];
        float gsum = 0.0f;
        #pragma unroll
        for (int t = 0; t < 2; t++) {
            int p = lane + 32 * t;
            if (p < HW) {
                float pd = fmaxf(A0s + rD0[p] + b0, 0.0f);
                float pa = fmaxf(A1s + rD1[p] + b1, 0.0f);
                if (p == pstar) { pd = 0.0f; pa = 0.0f; }
                float ri = ((float)(p / 7) - ai) * (1.0f / 7.0f);
                float rj = ((float)(p % 7) - aj) * (1.0f / 7.0f);
                float rd = sqrtf(ri * ri + rj * rj);
                float ra = (atan2f(rj, ri) * inv_pi + 1.0f) * 0.5f;
                float g  = pa - ra;
                if (g < 0.0f) g += 1.0f;
                float dl = pd - rd;
                dist[t] = dl * dl;
                gap[t]  = g;
                gsum   += g;
            } else {
                dist[t] = 0.0f; gap[t] = 0.0f;
            }
        }
        #pragma unroll
        for (int off = 16; off; off >>= 1) gsum += __shfl_xor_sync(0xFFFFFFFFu, gsum, off);
        const float gmean = gsum * (1.0f / 49.0f);

        #pragma unroll
        for (int t = 0; t < 2; t++) {
            int p = lane + 32 * t;
            if (p < HW) {
                float gg = gap[t] - gmean;
                out[n * HW + p] = dist[t] + gg * gg;
            }
        }
    }
}

extern "C" void kernel_launch(void* const* d_in, const int* in_sizes, int n_in,
                              void* d_out, int out_size) {
    const float* x    = (const float*)d_in[0];   // (256, 2048, 7, 7)
    const float* mask = (const float*)d_in[1];   // (256, 7, 7)
    const float* W    = (const float*)d_in[2];   // (2, 4096)
    const float* b    = (const float*)d_in[3];   // (2,)
    float* out = (float*)d_out;                  // (256, 7, 7)

    cudaFuncSetAttribute(rcp_ws_kernel,
                         cudaFuncAttributeMaxDynamicSharedMemorySize, SMEM_BYTES);

    rcp_ws_kernel<<<N_BATCH, THREADS, SMEM_BYTES>>>(x, mask, W, b, out);
}